// round 2
// baseline (speedup 1.0000x reference)
#include <cuda_runtime.h>

// Problem constants
#define BDIM      2048
#define T_IN      48
#define FEAT      64
#define UNITS     1024
#define G4        4096        // 4 * UNITS
#define OUT_STEPS 64

// Cell GEMM tiling
#define BM 64     // batch rows per block
#define BU 32     // units per block -> BN = 128 gate columns
#define BN 128
#define KT 32     // K tile

// Persistent state (scratch via __device__ globals; no allocations allowed)
__device__ float g_h[2][BDIM * UNITS];   // double-buffered hidden state
__device__ float g_c[BDIM * UNITS];      // cell state (updated in place)
__device__ float g_Ueff[UNITS * G4];     // U + Wd@W  (decode recurrence weight)
__device__ float g_beff[G4];             // b + bd@W

// ---------------------------------------------------------------------------
// Math helpers (fp32 accurate: __expf has ~2^-21 rel err)
// ---------------------------------------------------------------------------
__device__ __forceinline__ float sigf(float x) { return 1.0f / (1.0f + __expf(-x)); }
__device__ __forceinline__ float tanh_(float x) { return 2.0f * sigf(2.0f * x) - 1.0f; }

// Packed f32x2 helpers (Blackwell FFMA2: 2 FMAs per instruction, rt_SMSP=2)
__device__ __forceinline__ unsigned long long pack2(float x) {
    unsigned int xi = __float_as_uint(x);
    unsigned long long r;
    asm("mov.b64 %0, {%1, %2};" : "=l"(r) : "r"(xi), "r"(xi));
    return r;
}
__device__ __forceinline__ void unpack2(unsigned long long v, float& lo, float& hi) {
    unsigned int a, b;
    asm("mov.b64 {%0, %1}, %2;" : "=r"(a), "=r"(b) : "l"(v));
    lo = __uint_as_float(a);
    hi = __uint_as_float(b);
}
__device__ __forceinline__ unsigned long long fma2(unsigned long long a,
                                                   unsigned long long b,
                                                   unsigned long long c) {
    unsigned long long d;
    asm("fma.rn.f32x2 %0, %1, %2, %3;" : "=l"(d) : "l"(a), "l"(b), "l"(c));
    return d;
}

// ---------------------------------------------------------------------------
// init: zero h0, c0 (must be re-done every launch for determinism)
// ---------------------------------------------------------------------------
__global__ void init_kernel() {
    int n = BDIM * UNITS;
    for (int i = blockIdx.x * blockDim.x + threadIdx.x; i < n; i += gridDim.x * blockDim.x) {
        g_h[0][i] = 0.0f;
        g_c[i] = 0.0f;
    }
}

// ---------------------------------------------------------------------------
// prologue: Ueff = U + Wd @ W   ([1024,4096]); beff = b + bd @ W
// Removes the prediction GEMM from the decode critical path.
// ---------------------------------------------------------------------------
__global__ void prep_ueff(const float* __restrict__ U,
                          const float* __restrict__ Wd,
                          const float* __restrict__ W) {
    __shared__ float wd[FEAT];
    int u = blockIdx.x;
    if (threadIdx.x < FEAT) wd[threadIdx.x] = Wd[u * FEAT + threadIdx.x];
    __syncthreads();
    for (int j = threadIdx.x; j < G4; j += blockDim.x) {
        float acc = U[(long)u * G4 + j];
#pragma unroll 16
        for (int k = 0; k < FEAT; k++) acc += wd[k] * W[(long)k * G4 + j];
        g_Ueff[(long)u * G4 + j] = acc;
    }
}

__global__ void prep_beff(const float* __restrict__ b,
                          const float* __restrict__ bd,
                          const float* __restrict__ W) {
    int j = blockIdx.x * blockDim.x + threadIdx.x;
    if (j < G4) {
        float acc = b[j];
#pragma unroll 16
        for (int k = 0; k < FEAT; k++) acc += bd[k] * W[(long)k * G4 + j];
        g_beff[j] = acc;
    }
}

// ---------------------------------------------------------------------------
// Fused LSTM cell step:
//   z = [x@W +] h@Wrec + bias ;  gates ; update c (in place) and h (double buf)
// Tile: 64 rows x 32 units (=128 gate cols). 256 threads, 4x8 micro-tile each,
// gate columns interleaved (col = lu*4 + gate) so each thread owns complete
// (i,f,g,o) quadruples and performs the cell update locally.
// ---------------------------------------------------------------------------
template <bool HAS_X>
__global__ void __launch_bounds__(256, 2) cell_kernel(
    const float* __restrict__ x, int xstride,
    const float* __restrict__ W,
    const float* __restrict__ Wrec_in,
    const float* __restrict__ bias_in,
    int cur) {
    __shared__ __align__(16) float As[KT][BM + 4];  // transposed: As[k][row]
    __shared__ __align__(16) float Bs[KT][BN];      // Bs[k][lu*4+g]

    const float* __restrict__ Wrec = HAS_X ? Wrec_in : g_Ueff;
    const float* __restrict__ bias = HAS_X ? bias_in : g_beff;
    const float* __restrict__ hin  = g_h[cur];
    float* __restrict__ hout       = g_h[cur ^ 1];

    const int tid = threadIdx.x;
    const int tx = tid & 15, ty = tid >> 4;
    const int row0 = blockIdx.y * BM;
    const int u0 = blockIdx.x * BU;

    unsigned long long acc[4][4];
#pragma unroll
    for (int r = 0; r < 4; r++)
#pragma unroll
        for (int p = 0; p < 4; p++) acc[r][p] = 0ull;

    auto phase = [&](const float* __restrict__ P, int pstride,
                     const float* __restrict__ Wg, int KD) {
        for (int k0 = 0; k0 < KD; k0 += KT) {
            // A tile: 32x64, 8 elems/thread; global reads coalesced along k
#pragma unroll
            for (int i = 0; i < (KT * BM) / 256; i++) {
                int j = tid + i * 256;
                int r = j >> 5, k = j & 31;
                As[k][r] = P[(long)(row0 + r) * pstride + k0 + k];
            }
            // B tile: 32x128, 16 elems/thread; coalesced along lu (32 floats)
#pragma unroll
            for (int i = 0; i < (KT * BN) / 256; i++) {
                int j = tid + i * 256;
                int lu = j & 31, g = (j >> 5) & 3, k = j >> 7;
                Bs[k][lu * 4 + g] = Wg[(long)(k0 + k) * G4 + g * UNITS + u0 + lu];
            }
            __syncthreads();
#pragma unroll 8
            for (int k = 0; k < KT; k++) {
                float4 av = *reinterpret_cast<const float4*>(&As[k][ty * 4]);
                unsigned long long a2[4] = {pack2(av.x), pack2(av.y), pack2(av.z), pack2(av.w)};
                const unsigned long long* bp =
                    reinterpret_cast<const unsigned long long*>(&Bs[k][tx * 8]);
                unsigned long long b2[4] = {bp[0], bp[1], bp[2], bp[3]};
#pragma unroll
                for (int r = 0; r < 4; r++)
#pragma unroll
                    for (int p = 0; p < 4; p++) acc[r][p] = fma2(a2[r], b2[p], acc[r][p]);
            }
            __syncthreads();
        }
    };

    if (HAS_X) phase(x, xstride, W, FEAT);
    phase(hin, UNITS, Wrec, UNITS);

    // Epilogue: each thread owns rows ty*4..+3 and units {2tx, 2tx+1}
#pragma unroll
    for (int r = 0; r < 4; r++) {
        int row = row0 + ty * 4 + r;
#pragma unroll
        for (int s = 0; s < 2; s++) {
            int u = u0 + 2 * tx + s;
            float zi, zf, zg, zo;
            unpack2(acc[r][2 * s + 0], zi, zf);
            unpack2(acc[r][2 * s + 1], zg, zo);
            zi += bias[u];
            zf += bias[UNITS + u];
            zg += bias[2 * UNITS + u];
            zo += bias[3 * UNITS + u];
            long idx = (long)row * UNITS + u;
            float cn = sigf(zf) * g_c[idx] + sigf(zi) * tanh_(zg);
            float hn = sigf(zo) * tanh_(cn);
            g_c[idx] = cn;
            hout[idx] = hn;
        }
    }
}

// ---------------------------------------------------------------------------
// Prediction projection: out[:, t, :] = h @ Wd + bd   ([2048,1024]x[1024,64])
// Off the critical path (decode recurrence uses Ueff).
// ---------------------------------------------------------------------------
__global__ void __launch_bounds__(256) pred_kernel(float* __restrict__ out, int t, int cur,
                                                   const float* __restrict__ Wd,
                                                   const float* __restrict__ bd) {
    __shared__ __align__(16) float As[KT][36];
    __shared__ __align__(16) float Bs[KT][FEAT];
    const float* __restrict__ h = g_h[cur];
    const int tid = threadIdx.x;
    const int tx = tid & 15, ty = tid >> 4;
    const int row0 = blockIdx.x * 32;

    float acc[2][4] = {};
    for (int k0 = 0; k0 < UNITS; k0 += KT) {
#pragma unroll
        for (int i = 0; i < 4; i++) {
            int j = tid + i * 256;
            int r = j >> 5, k = j & 31;
            As[k][r] = h[(long)(row0 + r) * UNITS + k0 + k];
        }
#pragma unroll
        for (int i = 0; i < 8; i++) {
            int j = tid + i * 256;
            int f = j & 63, k = j >> 6;
            Bs[k][f] = Wd[(long)(k0 + k) * FEAT + f];
        }
        __syncthreads();
#pragma unroll 8
        for (int k = 0; k < KT; k++) {
            float a0 = As[k][ty * 2], a1 = As[k][ty * 2 + 1];
            float4 bv = *reinterpret_cast<const float4*>(&Bs[k][tx * 4]);
            acc[0][0] += a0 * bv.x; acc[0][1] += a0 * bv.y;
            acc[0][2] += a0 * bv.z; acc[0][3] += a0 * bv.w;
            acc[1][0] += a1 * bv.x; acc[1][1] += a1 * bv.y;
            acc[1][2] += a1 * bv.z; acc[1][3] += a1 * bv.w;
        }
        __syncthreads();
    }
#pragma unroll
    for (int r = 0; r < 2; r++) {
        int row = row0 + ty * 2 + r;
#pragma unroll
        for (int cc = 0; cc < 4; cc++) {
            int f = tx * 4 + cc;
            out[(long)row * OUT_STEPS * FEAT + (long)t * FEAT + f] = acc[r][cc] + bd[f];
        }
    }
}

// ---------------------------------------------------------------------------
// kernel_launch: graph-capturable sequence of launches only.
// Inputs (metadata order): inputs, W, U, b, Wd, bd. Output: [2048, 64, 64] f32.
// ---------------------------------------------------------------------------
extern "C" void kernel_launch(void* const* d_in, const int* in_sizes, int n_in,
                              void* d_out, int out_size) {
    const float* inputs = (const float*)d_in[0];
    const float* W      = (const float*)d_in[1];
    const float* U      = (const float*)d_in[2];
    const float* b      = (const float*)d_in[3];
    const float* Wd     = (const float*)d_in[4];
    const float* bd     = (const float*)d_in[5];
    float* out = (float*)d_out;

    init_kernel<<<256, 256>>>();
    prep_ueff<<<UNITS, 256>>>(U, Wd, W);
    prep_beff<<<G4 / 256, 256>>>(b, bd, W);

    dim3 cgrid(UNITS / BU, BDIM / BM);  // 32 x 32 = 1024 blocks
    int cur = 0;

    // Warmup: 48 steps over the input sequence (x @ W phase included)
    for (int t = 0; t < T_IN; t++) {
        cell_kernel<true><<<cgrid, 256>>>(inputs + (long)t * FEAT, T_IN * FEAT, W, U, b, cur);
        cur ^= 1;
    }

    // First prediction
    pred_kernel<<<BDIM / 32, 256>>>(out, 0, cur, Wd, bd);

    // Autoregressive decode: recurrence folds pred feedback into Ueff/beff,
    // so pred_kernel is a pure side output.
    for (int t = 1; t < OUT_STEPS; t++) {
        cell_kernel<false><<<cgrid, 256>>>(nullptr, 0, nullptr, nullptr, nullptr, cur);
        cur ^= 1;
        pred_kernel<<<BDIM / 32, 256>>>(out, t, cur, Wd, bd);
    }
}

// round 5
// speedup vs baseline: 1.3820x; 1.3820x over previous
#include <cuda_runtime.h>

// Problem constants
#define BDIM      2048
#define T_IN      48
#define FEAT      64
#define UNITS     1024
#define G4        4096
#define OUT_STEPS 64

// Cell GEMM tiling
#define BM 128    // batch rows per block
#define UB 32     // units per block (=> 128 gate columns)
#define KT 32     // K tile

// Persistent scratch (__device__ globals; no allocations allowed).
// State is stored TRANSPOSED: [unit][batch-row], so cell A-tiles load coalesced.
__device__ float g_h[2][UNITS * BDIM];
__device__ float g_c[UNITS * BDIM];
__device__ float g_Ueff[UNITS * G4];          // U + Wd@W
__device__ float g_beff[G4];                  // b + bd@W
__device__ float g_xT[T_IN * FEAT * BDIM];    // x transposed: [t*FEAT+k][row]

// ---------------------------------------------------------------------------
__device__ __forceinline__ float sigf(float x) { return 1.0f / (1.0f + __expf(-x)); }
__device__ __forceinline__ float tanh_(float x) { return 2.0f * sigf(2.0f * x) - 1.0f; }

__device__ __forceinline__ void unpack2(unsigned long long v, float& lo, float& hi) {
    unsigned int a, b;
    asm("mov.b64 {%0, %1}, %2;" : "=r"(a), "=r"(b) : "l"(v));
    lo = __uint_as_float(a);
    hi = __uint_as_float(b);
}
__device__ __forceinline__ unsigned long long fma2(unsigned long long a,
                                                   unsigned long long b,
                                                   unsigned long long c) {
    unsigned long long d;
    asm("fma.rn.f32x2 %0, %1, %2, %3;" : "=l"(d) : "l"(a), "l"(b), "l"(c));
    return d;
}

// ---------------------------------------------------------------------------
__global__ void init_kernel() {
    int n = UNITS * BDIM;
    for (int i = blockIdx.x * blockDim.x + threadIdx.x; i < n; i += gridDim.x * blockDim.x) {
        g_h[0][i] = 0.0f;
        g_c[i] = 0.0f;
    }
}

// Transpose inputs [2048][48*64] -> g_xT [48*64][2048]
__global__ void transpose_x(const float* __restrict__ in) {
    __shared__ float tile[32][33];
    int c0 = blockIdx.x * 32;   // column in [0, 3072)
    int r0 = blockIdx.y * 32;   // row in [0, 2048)
    int lx = threadIdx.x & 31, ly0 = threadIdx.x >> 5;
#pragma unroll
    for (int i = 0; i < 4; i++) {
        int ly = ly0 + i * 8;
        tile[ly][lx] = in[(size_t)(r0 + ly) * (T_IN * FEAT) + c0 + lx];
    }
    __syncthreads();
#pragma unroll
    for (int i = 0; i < 4; i++) {
        int ly = ly0 + i * 8;
        g_xT[(size_t)(c0 + ly) * BDIM + r0 + lx] = tile[lx][ly];
    }
}

// ---------------------------------------------------------------------------
// prologue: Ueff = U + Wd @ W ; beff = b + bd @ W
// ---------------------------------------------------------------------------
__global__ void prep_ueff(const float* __restrict__ U,
                          const float* __restrict__ Wd,
                          const float* __restrict__ W) {
    __shared__ float wd[FEAT];
    int u = blockIdx.x;
    if (threadIdx.x < FEAT) wd[threadIdx.x] = Wd[u * FEAT + threadIdx.x];
    __syncthreads();
    for (int j = threadIdx.x; j < G4; j += blockDim.x) {
        float acc = U[(size_t)u * G4 + j];
#pragma unroll 16
        for (int k = 0; k < FEAT; k++) acc += wd[k] * W[(size_t)k * G4 + j];
        g_Ueff[(size_t)u * G4 + j] = acc;
    }
}

__global__ void prep_beff(const float* __restrict__ b,
                          const float* __restrict__ bd,
                          const float* __restrict__ W) {
    int j = blockIdx.x * blockDim.x + threadIdx.x;
    if (j < G4) {
        float acc = b[j];
#pragma unroll 16
        for (int k = 0; k < FEAT; k++) acc += bd[k] * W[(size_t)k * G4 + j];
        g_beff[j] = acc;
    }
}

// ---------------------------------------------------------------------------
// Fused LSTM cell step (conflict-free smem, 8x8 micro-tile, packed f32x2).
//   A (rows x K): plain [k][row] in smem -> LDS.128 gives natural row-pairs.
//   B (K x gatecols): gate-blocked, PRE-DUPLICATED: Bd[k][g][unit] = (w,w).
// Thread (tx,ty): rows 8*ty..+7 (as 4 f32x2 pairs), units {2tx, 2tx+1}, 4 gates.
// ---------------------------------------------------------------------------
template <bool HAS_X>
__global__ void __launch_bounds__(256, 2) cell_kernel(
    int t, const float* __restrict__ W,
    const float* __restrict__ U_in, const float* __restrict__ b_in, int cur) {
    __shared__ __align__(16) float As[KT][BM];                     // 16 KB
    __shared__ __align__(16) unsigned long long Bd[KT][4][UB];     // 32 KB

    const float* __restrict__ Wrec = HAS_X ? U_in : g_Ueff;
    const float* __restrict__ bias = HAS_X ? b_in : g_beff;
    const float* __restrict__ hin  = g_h[cur];
    float* __restrict__ hout       = g_h[cur ^ 1];

    const int tid = threadIdx.x;
    const int tx = tid & 15, ty = tid >> 4;
    const int row0 = blockIdx.y * BM;
    const int u0 = blockIdx.x * UB;

    unsigned long long acc[4][2][4];  // [rowpair][unit][gate]
#pragma unroll
    for (int rp = 0; rp < 4; rp++)
#pragma unroll
        for (int uu = 0; uu < 2; uu++)
#pragma unroll
            for (int g = 0; g < 4; g++) acc[rp][uu][g] = 0ull;

    auto phase = [&](const float* __restrict__ Asrc, const float* __restrict__ Bsrc, int KD) {
        for (int k0 = 0; k0 < KD; k0 += KT) {
            // A tile: [KT][BM] from transposed source — float4 both sides.
#pragma unroll
            for (int i = 0; i < 4; i++) {
                int f = tid + i * 256;
                int k = f >> 5, rq = f & 31;
                *reinterpret_cast<float4*>(&As[k][rq * 4]) =
                    *reinterpret_cast<const float4*>(&Asrc[(size_t)(k0 + k) * BDIM + row0 + rq * 4]);
            }
            // B tile: duplicated pairs, one STS.128 {x,x,y,y} per float2.
#pragma unroll
            for (int i = 0; i < 8; i++) {
                int f = tid + i * 256;
                int u2 = f & 15, g = (f >> 4) & 3, k = f >> 6;
                float2 w = *reinterpret_cast<const float2*>(
                    &Bsrc[(size_t)(k0 + k) * G4 + g * UNITS + u0 + u2 * 2]);
                float4 d = make_float4(w.x, w.x, w.y, w.y);
                *reinterpret_cast<float4*>(&Bd[k][g][u2 * 2]) = d;
            }
            __syncthreads();
#pragma unroll 8
            for (int k = 0; k < KT; k++) {
                const unsigned long long* ap =
                    reinterpret_cast<const unsigned long long*>(&As[k][ty * 8]);
                unsigned long long a0 = ap[0], a1 = ap[1], a2 = ap[2], a3 = ap[3];
#pragma unroll
                for (int g = 0; g < 4; g++) {
                    ulonglong2 bb = *reinterpret_cast<const ulonglong2*>(&Bd[k][g][tx * 2]);
                    acc[0][0][g] = fma2(a0, bb.x, acc[0][0][g]);
                    acc[0][1][g] = fma2(a0, bb.y, acc[0][1][g]);
                    acc[1][0][g] = fma2(a1, bb.x, acc[1][0][g]);
                    acc[1][1][g] = fma2(a1, bb.y, acc[1][1][g]);
                    acc[2][0][g] = fma2(a2, bb.x, acc[2][0][g]);
                    acc[2][1][g] = fma2(a2, bb.y, acc[2][1][g]);
                    acc[3][0][g] = fma2(a3, bb.x, acc[3][0][g]);
                    acc[3][1][g] = fma2(a3, bb.y, acc[3][1][g]);
                }
            }
            __syncthreads();
        }
    };

    if (HAS_X) phase(g_xT + (size_t)t * FEAT * BDIM, W, FEAT);
    phase(hin, Wrec, UNITS);

    // Epilogue: rows rbase..rbase+7 for units u0+2tx, u0+2tx+1 (transposed state).
    const int rbase = row0 + ty * 8;
#pragma unroll
    for (int uu = 0; uu < 2; uu++) {
        int unit = u0 + tx * 2 + uu;
        size_t base = (size_t)unit * BDIM + rbase;
        float4 co0 = *reinterpret_cast<const float4*>(&g_c[base]);
        float4 co1 = *reinterpret_cast<const float4*>(&g_c[base + 4]);
        float cold[8] = {co0.x, co0.y, co0.z, co0.w, co1.x, co1.y, co1.z, co1.w};
        float bi = bias[unit], bf = bias[UNITS + unit];
        float bg = bias[2 * UNITS + unit], bo = bias[3 * UNITS + unit];
        float cv[8], hv[8];
#pragma unroll
        for (int rp = 0; rp < 4; rp++) {
            float zi0, zi1, zf0, zf1, zg0, zg1, zo0, zo1;
            unpack2(acc[rp][uu][0], zi0, zi1);
            unpack2(acc[rp][uu][1], zf0, zf1);
            unpack2(acc[rp][uu][2], zg0, zg1);
            unpack2(acc[rp][uu][3], zo0, zo1);
            int r = rp * 2;
            cv[r]     = sigf(zf0 + bf) * cold[r]     + sigf(zi0 + bi) * tanh_(zg0 + bg);
            hv[r]     = sigf(zo0 + bo) * tanh_(cv[r]);
            cv[r + 1] = sigf(zf1 + bf) * cold[r + 1] + sigf(zi1 + bi) * tanh_(zg1 + bg);
            hv[r + 1] = sigf(zo1 + bo) * tanh_(cv[r + 1]);
        }
        *reinterpret_cast<float4*>(&g_c[base])     = make_float4(cv[0], cv[1], cv[2], cv[3]);
        *reinterpret_cast<float4*>(&g_c[base + 4]) = make_float4(cv[4], cv[5], cv[6], cv[7]);
        *reinterpret_cast<float4*>(&hout[base])     = make_float4(hv[0], hv[1], hv[2], hv[3]);
        *reinterpret_cast<float4*>(&hout[base + 4]) = make_float4(hv[4], hv[5], hv[6], hv[7]);
    }
}

// ---------------------------------------------------------------------------
// Prediction: out[:, t, :] = h^T^T @ Wd + bd.  32 rows x 64 feat per block.
// ---------------------------------------------------------------------------
__global__ void __launch_bounds__(256) pred_kernel(float* __restrict__ out, int t, int cur,
                                                   const float* __restrict__ Wd,
                                                   const float* __restrict__ bd) {
    __shared__ __align__(16) float Ah[64][32];   // [k][row] 8 KB
    __shared__ __align__(16) float Bw[64][FEAT]; // 16 KB
    const float* __restrict__ h = g_h[cur];
    const int tid = threadIdx.x;
    const int tx = tid & 15, ty = tid >> 4;
    const int row0 = blockIdx.x * 32;

    float acc[2][4] = {};
    for (int k0 = 0; k0 < UNITS; k0 += 64) {
#pragma unroll
        for (int i = 0; i < 2; i++) {
            int f = tid + i * 256;
            int k = f >> 3, rq = f & 7;
            *reinterpret_cast<float4*>(&Ah[k][rq * 4]) =
                *reinterpret_cast<const float4*>(&h[(size_t)(k0 + k) * BDIM + row0 + rq * 4]);
        }
#pragma unroll
        for (int i = 0; i < 4; i++) {
            int f = tid + i * 256;
            int k = f >> 4, fq = f & 15;
            *reinterpret_cast<float4*>(&Bw[k][fq * 4]) =
                *reinterpret_cast<const float4*>(&Wd[(size_t)(k0 + k) * FEAT + fq * 4]);
        }
        __syncthreads();
#pragma unroll 8
        for (int k = 0; k < 64; k++) {
            float a0 = Ah[k][ty * 2], a1 = Ah[k][ty * 2 + 1];
            float4 bv = *reinterpret_cast<const float4*>(&Bw[k][tx * 4]);
            acc[0][0] += a0 * bv.x; acc[0][1] += a0 * bv.y;
            acc[0][2] += a0 * bv.z; acc[0][3] += a0 * bv.w;
            acc[1][0] += a1 * bv.x; acc[1][1] += a1 * bv.y;
            acc[1][2] += a1 * bv.z; acc[1][3] += a1 * bv.w;
        }
        __syncthreads();
    }
    float4 bdv = *reinterpret_cast<const float4*>(&bd[tx * 4]);
#pragma unroll
    for (int r = 0; r < 2; r++) {
        int row = row0 + ty * 2 + r;
        float4 o = make_float4(acc[r][0] + bdv.x, acc[r][1] + bdv.y,
                               acc[r][2] + bdv.z, acc[r][3] + bdv.w);
        *reinterpret_cast<float4*>(&out[(size_t)row * (OUT_STEPS * FEAT) + t * FEAT + tx * 4]) = o;
    }
}

// ---------------------------------------------------------------------------
extern "C" void kernel_launch(void* const* d_in, const int* in_sizes, int n_in,
                              void* d_out, int out_size) {
    const float* inputs = (const float*)d_in[0];
    const float* W      = (const float*)d_in[1];
    const float* U      = (const float*)d_in[2];
    const float* b      = (const float*)d_in[3];
    const float* Wd     = (const float*)d_in[4];
    const float* bd     = (const float*)d_in[5];
    float* out = (float*)d_out;

    init_kernel<<<512, 256>>>();
    transpose_x<<<dim3((T_IN * FEAT) / 32, BDIM / 32), 256>>>(inputs);
    prep_ueff<<<UNITS, 256>>>(U, Wd, W);
    prep_beff<<<G4 / 256, 256>>>(b, bd, W);

    dim3 cgrid(UNITS / UB, BDIM / BM);  // 32 x 16 = 512 blocks
    int cur = 0;

    for (int t = 0; t < T_IN; t++) {
        cell_kernel<true><<<cgrid, 256>>>(t, W, U, b, cur);
        cur ^= 1;
    }

    pred_kernel<<<BDIM / 32, 256>>>(out, 0, cur, Wd, bd);

    for (int t = 1; t < OUT_STEPS; t++) {
        cell_kernel<false><<<cgrid, 256>>>(0, nullptr, nullptr, nullptr, cur);
        cur ^= 1;
        pred_kernel<<<BDIM / 32, 256>>>(out, t, cur, Wd, bd);
    }
}

// round 12
// speedup vs baseline: 3.2082x; 2.3215x over previous
#include <cuda_runtime.h>
#include <cuda_bf16.h>
#include <cstdint>

// Problem constants
#define BDIM      2048
#define T_IN      48
#define FEAT      64
#define UNITS     1024
#define G4        4096
#define OUT_STEPS 64

#define NCHW 17          // warmup base K chunks: (64 + 1024)/64
#define NCHD 16          // decode base K chunks: 1024/64
#define MT   128         // M tile (batch rows per CTA)
#define NT   128         // N tile (gate cols per CTA) = 32 units
#define SMEM_TOTAL 67584 // max(2*(16K A + 16K B) = 64K, stage 128*132*4 = 66K)

// ---------------------------------------------------------------------------
// Persistent scratch (__device__ globals; no allocations allowed)
// ---------------------------------------------------------------------------
__device__ float          g_c   [BDIM * UNITS];            // cell state fp32 [batch][unit]
__device__ float          g_hf  [2][BDIM * UNITS];         // h fp32 (for pred)
__device__ __nv_bfloat16  g_hhi [2][BDIM * UNITS];         // h hi bf16 [batch][unit]
__device__ __nv_bfloat16  g_hlo [2][BDIM * UNITS];         // h lo bf16
__device__ __nv_bfloat16  g_xhi [BDIM * T_IN * FEAT];      // x split [batch][t*64+f]
__device__ __nv_bfloat16  g_xlo [BDIM * T_IN * FEAT];
__device__ float          g_Ueff[UNITS * G4];              // U + Wd@W (gate-blocked)
__device__ float          g_beff[G4];                      // b + bd@W
// Pre-swizzled, gate-interleaved (col' = 4u+g), chunk-tiled B (SW128, [n][k]):
__device__ __nv_bfloat16  g_Bw_hi[NCHW * G4 * 64];
__device__ __nv_bfloat16  g_Bw_lo[NCHW * G4 * 64];
__device__ __nv_bfloat16  g_Bd_hi[NCHD * G4 * 64];
__device__ __nv_bfloat16  g_Bd_lo[NCHD * G4 * 64];

// ---------------------------------------------------------------------------
// Helpers
// ---------------------------------------------------------------------------
__device__ __forceinline__ float sigf(float x) { return 1.0f / (1.0f + __expf(-x)); }
__device__ __forceinline__ float tanh_(float x) { return 2.0f * sigf(2.0f * x) - 1.0f; }

__device__ __forceinline__ uint32_t swz(uint32_t o) { return o ^ ((o >> 3) & 0x70); }

__device__ __forceinline__ uint32_t smem_u32(const void* p) {
    uint32_t a;
    asm("{ .reg .u64 t; cvta.to.shared.u64 t, %1; cvt.u32.u64 %0, t; }" : "=r"(a) : "l"(p));
    return a;
}
__device__ __forceinline__ void cp_async16(uint32_t dst, const void* src) {
    asm volatile("cp.async.cg.shared.global [%0], [%1], 16;"
                 :: "r"(dst), "l"(__cvta_generic_to_global(src)) : "memory");
}

#define LDSM4(r, addr) \
    asm volatile("ldmatrix.sync.aligned.m8n8.x4.shared.b16 {%0,%1,%2,%3}, [%4];" \
                 : "=r"((r)[0]), "=r"((r)[1]), "=r"((r)[2]), "=r"((r)[3]) : "r"(addr))

#define MMA16816(d, a, b) \
    asm volatile("mma.sync.aligned.m16n8k16.row.col.f32.bf16.bf16.f32 " \
                 "{%0,%1,%2,%3},{%4,%5,%6,%7},{%8,%9},{%0,%1,%2,%3};" \
                 : "+f"((d)[0]), "+f"((d)[1]), "+f"((d)[2]), "+f"((d)[3]) \
                 : "r"((a)[0]), "r"((a)[1]), "r"((a)[2]), "r"((a)[3]), \
                   "r"((b)[0]), "r"((b)[1]))

// ---------------------------------------------------------------------------
// Prologue kernels
// ---------------------------------------------------------------------------
__global__ void init_kernel() {
    int n = BDIM * UNITS;
    for (int i = blockIdx.x * blockDim.x + threadIdx.x; i < n; i += gridDim.x * blockDim.x) {
        g_c[i] = 0.0f;
        g_hhi[0][i] = __float2bfloat16(0.0f);
        g_hlo[0][i] = __float2bfloat16(0.0f);
    }
}

__global__ void split_x(const float* __restrict__ in) {
    int n = BDIM * T_IN * FEAT;
    for (int i = blockIdx.x * blockDim.x + threadIdx.x; i < n; i += gridDim.x * blockDim.x) {
        float v = in[i];
        __nv_bfloat16 hi = __float2bfloat16(v);
        g_xhi[i] = hi;
        g_xlo[i] = __float2bfloat16(v - __bfloat162float(hi));
    }
}

__global__ void prep_ueff(const float* __restrict__ U, const float* __restrict__ Wd,
                          const float* __restrict__ W) {
    __shared__ float wd[FEAT];
    int u = blockIdx.x;
    if (threadIdx.x < FEAT) wd[threadIdx.x] = Wd[u * FEAT + threadIdx.x];
    __syncthreads();
    for (int j = threadIdx.x; j < G4; j += blockDim.x) {
        float acc = U[(size_t)u * G4 + j];
#pragma unroll 16
        for (int k = 0; k < FEAT; k++) acc += wd[k] * W[(size_t)k * G4 + j];
        g_Ueff[(size_t)u * G4 + j] = acc;
    }
}

__global__ void prep_beff(const float* __restrict__ b, const float* __restrict__ bd,
                          const float* __restrict__ W) {
    int j = blockIdx.x * blockDim.x + threadIdx.x;
    if (j < G4) {
        float acc = b[j];
#pragma unroll 16
        for (int k = 0; k < FEAT; k++) acc += bd[k] * W[(size_t)k * G4 + j];
        g_beff[j] = acc;
    }
}

// Build warmup B (chunk-tiled [n][k64], gate-interleaved col'=4u+g, SW128-pre-swizzled)
__global__ void build_Bw(const float* __restrict__ W, const float* __restrict__ U) {
    int total = NCHW * 64 * G4;
    for (int idx = blockIdx.x * blockDim.x + threadIdx.x; idx < total;
         idx += gridDim.x * blockDim.x) {
        int kp = idx >> 12, n = idx & 4095;       // kp in [0,1088)
        int g = n & 3, u = n >> 2;
        int j = g * UNITS + u;
        float v = (kp < FEAT) ? W[(size_t)kp * G4 + j] : U[(size_t)(kp - FEAT) * G4 + j];
        __nv_bfloat16 hi = __float2bfloat16(v);
        __nv_bfloat16 lo = __float2bfloat16(v - __bfloat162float(hi));
        int kc = kp >> 6, kl = kp & 63;
        size_t off = (size_t)kc * (G4 * 64) + (swz((uint32_t)n * 128 + kl * 2) >> 1);
        g_Bw_hi[off] = hi;
        g_Bw_lo[off] = lo;
    }
}

__global__ void build_Bd() {
    int total = NCHD * 64 * G4;
    for (int idx = blockIdx.x * blockDim.x + threadIdx.x; idx < total;
         idx += gridDim.x * blockDim.x) {
        int kp = idx >> 12, n = idx & 4095;       // kp in [0,1024)
        int g = n & 3, u = n >> 2;
        float v = g_Ueff[(size_t)kp * G4 + g * UNITS + u];
        __nv_bfloat16 hi = __float2bfloat16(v);
        __nv_bfloat16 lo = __float2bfloat16(v - __bfloat162float(hi));
        int kc = kp >> 6, kl = kp & 63;
        size_t off = (size_t)kc * (G4 * 64) + (swz((uint32_t)n * 128 + kl * 2) >> 1);
        g_Bd_hi[off] = hi;
        g_Bd_lo[off] = lo;
    }
}

// ---------------------------------------------------------------------------
// mma.sync fused LSTM cell step.
// Z = [Ahi|Ahi|Alo] @ [Bhi;Blo;Bhi]  (bf16 split, fp32 register accum)
// CTA tile: M=128 x N=128 gate cols (32 units, col'=4u+gate).
// 8 warps (4m x 2n), warp tile 32x64, m16n8k16 HMMA, cp.async double-buffer.
// Epilogue: frags -> smem stage -> fused gates -> h/c update.
// ---------------------------------------------------------------------------
template <bool WARMUP>
__global__ void __launch_bounds__(256, 2) cell_mma(int step, int cur,
                                                   const float* __restrict__ bias_in) {
    extern __shared__ char smem[];
    const uint32_t sb = smem_u32(smem);
    float* stage = reinterpret_cast<float*>(smem);
    const int tid = threadIdx.x;
    const int m0 = blockIdx.y * MT;
    const int n0 = blockIdx.x * NT;
    const int ubase = blockIdx.x * (NT / 4);
    const int NCH = WARMUP ? NCHW : NCHD;
    const int TOTAL = 3 * NCH;

    const __nv_bfloat16* __restrict__ hhi = g_hhi[cur];
    const __nv_bfloat16* __restrict__ hlo = g_hlo[cur];

    const uint32_t slotA[2] = {0u, 32768u};
    const uint32_t slotB[2] = {16384u, 49152u};

    auto issue_chunk = [&](int c) {
        int slot = c & 1;
        int term = c / NCH;
        int kc = c - term * NCH;
        const __nv_bfloat16* Asrc;
        int astride, aoffk;
        if (WARMUP && kc == 0) {
            Asrc = (term < 2) ? g_xhi : g_xlo;
            astride = T_IN * FEAT;
            aoffk = step * FEAT;
        } else {
            Asrc = (term < 2) ? hhi : hlo;
            astride = UNITS;
            aoffk = (WARMUP ? (kc - 1) : kc) * 64;
        }
        const __nv_bfloat16* Bsrc = WARMUP ? ((term == 1) ? g_Bw_lo : g_Bw_hi)
                                           : ((term == 1) ? g_Bd_lo : g_Bd_hi);
        // A tile: 128 rows x 64 bf16, SW128 swizzle on 16B units
#pragma unroll
        for (int i = 0; i < 4; i++) {
            int f = tid + i * 256;
            int r = f >> 3, q = f & 7;
            uint32_t dst = sb + slotA[slot] + r * 128 + ((q * 16) ^ ((r & 7) * 16));
            cp_async16(dst, Asrc + (size_t)(m0 + r) * astride + aoffk + q * 8);
        }
        // B tile: 128 rows x 64 bf16, pre-swizzled global -> straight copy
        const __nv_bfloat16* bchunk = Bsrc + (size_t)kc * (G4 * 64) + (size_t)n0 * 64;
#pragma unroll
        for (int i = 0; i < 4; i++) {
            int f = tid + i * 256;
            cp_async16(sb + slotB[slot] + f * 16, bchunk + f * 8);
        }
        asm volatile("cp.async.commit_group;" ::: "memory");
    };

    float acc[2][8][4];
#pragma unroll
    for (int mt = 0; mt < 2; mt++)
#pragma unroll
        for (int nt = 0; nt < 8; nt++)
#pragma unroll
            for (int e = 0; e < 4; e++) acc[mt][nt][e] = 0.0f;

    const int lane = tid & 31, warp = tid >> 5;
    const int wm = warp >> 1, wn = warp & 1;      // 4 x 2 warp grid
    const int lrow = lane & 15;
    const int lk = (lane >> 4) * 16;              // upper-k byte offset for x4

    issue_chunk(0);
    for (int c = 0; c < TOTAL; c++) {
        if (c + 1 < TOTAL) {
            issue_chunk(c + 1);
            asm volatile("cp.async.wait_group 1;" ::: "memory");
        } else {
            asm volatile("cp.async.wait_group 0;" ::: "memory");
        }
        __syncthreads();
        const uint32_t Abase = sb + slotA[c & 1];
        const uint32_t Bbase = sb + slotB[c & 1];
#pragma unroll
        for (int ks = 0; ks < 4; ks++) {
            const int kb = ks * 32 + lk;
            uint32_t a[2][4];
#pragma unroll
            for (int mt = 0; mt < 2; mt++) {
                int row = wm * 32 + mt * 16 + lrow;
                LDSM4(a[mt], Abase + row * 128 + (kb ^ ((row & 7) * 16)));
            }
            uint32_t b[8][2];
#pragma unroll
            for (int np = 0; np < 4; np++) {
                int nrow = wn * 64 + np * 16 + lrow;
                uint32_t r[4];
                LDSM4(r, Bbase + nrow * 128 + (kb ^ ((nrow & 7) * 16)));
                b[np * 2][0] = r[0];
                b[np * 2 + 1][0] = r[1];
                b[np * 2][1] = r[2];
                b[np * 2 + 1][1] = r[3];
            }
#pragma unroll
            for (int mt = 0; mt < 2; mt++)
#pragma unroll
                for (int nt = 0; nt < 8; nt++) MMA16816(acc[mt][nt], a[mt], b[nt]);
        }
        __syncthreads();
    }

    // ---- Epilogue: frags -> stage (stride 132 to avoid bank conflicts) ----
    const int S = 132;
    const int g = lane >> 2, tg = lane & 3;
#pragma unroll
    for (int mt = 0; mt < 2; mt++)
#pragma unroll
        for (int nt = 0; nt < 8; nt++) {
            int row = wm * 32 + mt * 16 + g;
            int col = wn * 64 + nt * 8 + 2 * tg;
            *reinterpret_cast<float2*>(&stage[row * S + col]) =
                make_float2(acc[mt][nt][0], acc[mt][nt][1]);
            *reinterpret_cast<float2*>(&stage[(row + 8) * S + col]) =
                make_float2(acc[mt][nt][2], acc[mt][nt][3]);
        }
    __syncthreads();

    // gates + state update: thread -> unit (tid&31), rows tid>>5 + 8*it
    const float* __restrict__ bias = WARMUP ? bias_in : g_beff;
    float* __restrict__ hf = g_hf[cur ^ 1];
    __nv_bfloat16* __restrict__ ohi = g_hhi[cur ^ 1];
    __nv_bfloat16* __restrict__ olo = g_hlo[cur ^ 1];

    const int u = tid & 31;
    const int unit = ubase + u;
    const float bi = bias[unit], bff = bias[UNITS + unit];
    const float bg = bias[2 * UNITS + unit], bo = bias[3 * UNITS + unit];
#pragma unroll 4
    for (int it = 0; it < 16; it++) {
        int r = (tid >> 5) + it * 8;
        float4 z = *reinterpret_cast<const float4*>(&stage[r * S + 4 * u]);
        size_t idx = (size_t)(m0 + r) * UNITS + unit;
        float cold = g_c[idx];
        float cn = sigf(z.y + bff) * cold + sigf(z.x + bi) * tanh_(z.z + bg);
        float hn = sigf(z.w + bo) * tanh_(cn);
        g_c[idx] = cn;
        hf[idx] = hn;
        __nv_bfloat16 hb = __float2bfloat16(hn);
        ohi[idx] = hb;
        olo[idx] = __float2bfloat16(hn - __bfloat162float(hb));
    }
}

// ---------------------------------------------------------------------------
// Prediction: out[:, t, :] = h @ Wd + bd.  h fp32 natural [batch][unit].
// ---------------------------------------------------------------------------
__global__ void __launch_bounds__(256) pred_kernel(float* __restrict__ out, int t, int cur,
                                                   const float* __restrict__ Wd,
                                                   const float* __restrict__ bd) {
    __shared__ __align__(16) float As[64][68];
    __shared__ __align__(16) float Bs[64][FEAT];
    const float* __restrict__ h = g_hf[cur];
    const int tid = threadIdx.x;
    const int tx = tid & 15, ty = tid >> 4;
    const int row0 = blockIdx.x * 64;

    float acc[4][4] = {};
    for (int k0 = 0; k0 < UNITS; k0 += 64) {
#pragma unroll
        for (int i = 0; i < 4; i++) {
            int f = tid + i * 256;
            int r = f >> 4, q = f & 15;
            *reinterpret_cast<float4*>(&As[r][q * 4]) =
                *reinterpret_cast<const float4*>(&h[(size_t)(row0 + r) * UNITS + k0 + q * 4]);
        }
#pragma unroll
        for (int i = 0; i < 4; i++) {
            int f = tid + i * 256;
            int k = f >> 4, q = f & 15;
            *reinterpret_cast<float4*>(&Bs[k][q * 4]) =
                *reinterpret_cast<const float4*>(&Wd[(size_t)(k0 + k) * FEAT + q * 4]);
        }
        __syncthreads();
#pragma unroll 8
        for (int k = 0; k < 64; k++) {
            float4 bv = *reinterpret_cast<const float4*>(&Bs[k][tx * 4]);
#pragma unroll
            for (int rr = 0; rr < 4; rr++) {
                float a = As[ty * 4 + rr][k];
                acc[rr][0] += a * bv.x;
                acc[rr][1] += a * bv.y;
                acc[rr][2] += a * bv.z;
                acc[rr][3] += a * bv.w;
            }
        }
        __syncthreads();
    }
    float4 bdv = *reinterpret_cast<const float4*>(&bd[tx * 4]);
#pragma unroll
    for (int rr = 0; rr < 4; rr++) {
        int row = row0 + ty * 4 + rr;
        float4 o = make_float4(acc[rr][0] + bdv.x, acc[rr][1] + bdv.y,
                               acc[rr][2] + bdv.z, acc[rr][3] + bdv.w);
        *reinterpret_cast<float4*>(&out[(size_t)row * (OUT_STEPS * FEAT) + t * FEAT + tx * 4]) = o;
    }
}

// ---------------------------------------------------------------------------
extern "C" void kernel_launch(void* const* d_in, const int* in_sizes, int n_in,
                              void* d_out, int out_size) {
    const float* inputs = (const float*)d_in[0];
    const float* W      = (const float*)d_in[1];
    const float* U      = (const float*)d_in[2];
    const float* b      = (const float*)d_in[3];
    const float* Wd     = (const float*)d_in[4];
    const float* bd     = (const float*)d_in[5];
    float* out = (float*)d_out;

    cudaFuncSetAttribute((const void*)cell_mma<true>,
                         cudaFuncAttributeMaxDynamicSharedMemorySize, SMEM_TOTAL);
    cudaFuncSetAttribute((const void*)cell_mma<false>,
                         cudaFuncAttributeMaxDynamicSharedMemorySize, SMEM_TOTAL);

    init_kernel<<<512, 256>>>();
    split_x<<<512, 256>>>(inputs);
    prep_ueff<<<UNITS, 256>>>(U, Wd, W);
    prep_beff<<<G4 / 256, 256>>>(b, bd, W);
    build_Bw<<<1024, 256>>>(W, U);
    build_Bd<<<1024, 256>>>();

    dim3 grid(G4 / NT, BDIM / MT);  // 32 x 16 = 512 CTAs
    int cur = 0;

    for (int t = 0; t < T_IN; t++) {
        cell_mma<true><<<grid, 256, SMEM_TOTAL>>>(t, cur, b);
        cur ^= 1;
    }
    pred_kernel<<<BDIM / 64, 256>>>(out, 0, cur, Wd, bd);
    for (int t = 1; t < OUT_STEPS; t++) {
        cell_mma<false><<<grid, 256, SMEM_TOTAL>>>(0, cur, b);
        cur ^= 1;
        pred_kernel<<<BDIM / 64, 256>>>(out, t, cur, Wd, bd);
    }
}